// round 10
// baseline (speedup 1.0000x reference)
#include <cuda_runtime.h>
#include <math.h>

#define TT 256
#define BB 512
#define DD 64
#define G3 300
#define ST 68
#define DS 104
#define NCTA 128
#define NTHR 320
#define MAXOPS 4096
#define SMF 53172   // total shared floats in k_exec

__device__ float g_state[(size_t)TT * BB * ST];
__device__ float g_dict[(size_t)(TT + 1) * BB * DS];
__device__ int4  g_prog[MAXOPS];
__device__ int   g_nops;

// Repack a[B,D,T,3] -> g_state[t][b][c] (c<64 data, c==64 mask), zero dict[T].
__global__ void k_build(const float* __restrict__ a) {
    size_t i = (size_t)blockIdx.x * blockDim.x + threadIdx.x;
    const size_t n_state = (size_t)TT * BB * ST;
    if (i < n_state) {
        int t = (int)(i % TT);
        size_t r = i / TT;
        int c = (int)(r % ST);
        int b = (int)(r / ST);
        float v = 0.f;
        if (c < DD)       v = a[(((size_t)b * DD + c) * TT + t) * 3];
        else if (c == DD) v = a[(((size_t)b * DD) * TT + t) * 3 + 2];
        g_state[((size_t)t * BB + b) * ST + c] = v;
    } else if (i < n_state + (size_t)BB * DS) {
        g_dict[(size_t)TT * BB * DS + (i - n_state)] = 0.f;
    }
}

// Replay reference control flow; emit op list.
// op.x: 0=BACK (y=state idx or -1 for zeros, z=dict dst, reads dict[z+1])
//       1=FWD  (y=t, consumes state[t][1..64])
//       2=DEC  (y=mid, z=hb dict idx, w=level)
__global__ void k_sched(const float* __restrict__ a) {
    __shared__ unsigned char obs[TT];
    int t = threadIdx.x;
    if (t < TT) obs[t] = (a[(size_t)t * 3 + 2] > 0.5f) ? 1 : 0;
    __syncthreads();
    if (t != 0) return;
    int n = 0;
    for (int k = TT - 1; k >= 2; --k) g_prog[n++] = make_int4(0, k, k, 0);
    g_prog[n++] = make_int4(1, 0, 0, 0);
    int curr = 0;
    while (curr < TT - 1) {
        if (obs[curr + 1]) {
            ++curr;
            g_prog[n++] = make_int4(1, curr, 0, 0);
        } else {
            int next_p = curr + 1;
            while (next_p < TT && !obs[next_p]) ++next_p;
            int step = 1;
            while (curr + 2 * step <= next_p && step <= 8) step *= 2;
            if (step > 1) step /= 2;
            int lvl = 0; { int s = step; while (s > 1) { s >>= 1; ++lvl; } }
            int mid = curr + step;
            g_prog[n++] = make_int4(2, mid, curr + 2 * step, lvl);
            if (step > 1) {
                int right = mid, left = curr + step / 2;
                g_prog[n++] = make_int4(0, right, right, 0);
                for (int i2 = right - 1; i2 >= left; --i2)
                    g_prog[n++] = make_int4(0, -1, i2, 0);
            }
            obs[mid] = 1;
        }
    }
    g_nops = n;
}

__device__ __forceinline__ float sigm(float v) { return 1.f / (1.f + expf(-v)); }

__global__ void __launch_bounds__(NTHR, 1) k_exec(
    const float* __restrict__ gru_W,  const float* __restrict__ gru_U,  const float* __restrict__ gru_b,
    const float* __restrict__ bgru_W, const float* __restrict__ bgru_U, const float* __restrict__ bgru_b,
    const float* __restrict__ dec_W,  const float* __restrict__ dec_b,
    const float* __restrict__ mean_W, const float* __restrict__ mean_b)
{
    extern __shared__ float sm[];
    float* sW  = sm;             // 49500: bgru_W (65x300) + bgru_U (100x300), k-major
    float* sx  = sW + 49500;     // 272:   staged x, float4 per k
    float* sh  = sx + 272;       // 400:   fwd hidden  [j*4+b]
    float* shb = sh + 400;       // 400:   back hidden [j*4+b]
    float* sgx = shb + 400;      // 1200:  gate x-part [col*4+b]
    float* sgh = sgx + 1200;     // 1200:  gate h-part [col*4+b]
    float* sd  = sgh + 1200;     // 200:   decoder hidden
    const int tid = threadIdx.x;
    const int b0 = blockIdx.x * 4;

    for (int i = tid; i < 65 * G3; i += NTHR)  sW[i] = bgru_W[i];
    for (int i = tid; i < 100 * G3; i += NTHR) sW[19500 + i] = bgru_U[i];
    for (int i = tid; i < 400; i += NTHR) sh[i] = 0.f;
    __syncthreads();

    const int nops = g_nops;
    int hb_valid = -1;           // shb currently holds g_dict[hb_valid]
    for (int opi = 0; opi < nops; ++opi) {
        const int4 op = g_prog[opi];
        if (op.x == 2) {
            // DEC: mean = relu([h,hb] @ decW + decb) @ meanW + meanb -> state[mid]
            const int mid = op.y, hbi = op.z, lvl = op.w;
            if (hb_valid != hbi) {
                for (int i = tid; i < 400; i += NTHR) {
                    int j = i >> 2, b = i & 3;
                    shb[i] = g_dict[((size_t)hbi * BB + b0 + b) * DS + j];
                }
                hb_valid = hbi;
            }
            __syncthreads();
            if (tid < 200) {
                const int j = tid >> 2, b = tid & 3;
                float acc = __ldg(&dec_b[lvl * 50 + j]);
                const float* dw = dec_W + (size_t)lvl * 10000 + j;
                #pragma unroll 4
                for (int k = 0; k < 100; ++k) acc += sh[k * 4 + b] * __ldg(&dw[k * 50]);
                #pragma unroll 4
                for (int k = 0; k < 100; ++k) acc += shb[k * 4 + b] * __ldg(&dw[(100 + k) * 50]);
                sd[tid] = fmaxf(acc, 0.f);
            }
            __syncthreads();
            if (tid < 256) {
                const int j = tid >> 2, b = tid & 3;
                float acc = __ldg(&mean_b[lvl * DD + j]);
                const float* mw = mean_W + (size_t)lvl * 3200 + j;
                #pragma unroll 5
                for (int k = 0; k < 50; ++k) acc += sd[k * 4 + b] * __ldg(&mw[k * DD]);
                float* dst = &g_state[((size_t)mid * BB + b0 + b) * ST];
                dst[j] = acc;
                if (j == 0) dst[DD] = 1.f;
            }
            __syncthreads();
        } else {
            // GRU cell: FWD (op.x==1) or BACK (op.x==0)
            const bool fwd = (op.x == 1);
            const int t = op.y, dst = op.z;
            const bool hasx = (t >= 0);
            const int ID = fwd ? 64 : 65;
            if (hasx) {
                const int off = fwd ? 1 : 0;
                for (int i = tid; i < ID * 4; i += NTHR) {
                    int c = i >> 2, b = i & 3;
                    sx[c * 4 + b] = g_state[((size_t)t * BB + b0 + b) * ST + c + off];
                }
            }
            if (!fwd && hb_valid != dst + 1) {
                for (int i = tid; i < 400; i += NTHR) {
                    int j = i >> 2, b = i & 3;
                    shb[i] = g_dict[((size_t)(dst + 1) * BB + b0 + b) * DS + j];
                }
            }
            if (!fwd) hb_valid = dst + 1;
            __syncthreads();
            float* hcur = fwd ? sh : shb;
            if (tid < G3) {
                const int j = tid;
                const float* bias = fwd ? gru_b : bgru_b;
                float ax0 = __ldg(&bias[j]);      float ax1 = ax0, ax2 = ax0, ax3 = ax0;
                float ah0 = __ldg(&bias[G3 + j]); float ah1 = ah0, ah2 = ah0, ah3 = ah0;
                const float4* xv = (const float4*)sx;
                const float4* hv = (const float4*)hcur;
                if (hasx) {
                    if (fwd) {
                        const float* W = gru_W + j;
                        #pragma unroll 4
                        for (int k = 0; k < 64; ++k) {
                            float w = __ldg(&W[(size_t)k * G3]);
                            float4 x = xv[k];
                            ax0 += w * x.x; ax1 += w * x.y; ax2 += w * x.z; ax3 += w * x.w;
                        }
                    } else {
                        const float* W = sW + j;
                        #pragma unroll 5
                        for (int k = 0; k < 65; ++k) {
                            float w = W[k * G3];
                            float4 x = xv[k];
                            ax0 += w * x.x; ax1 += w * x.y; ax2 += w * x.z; ax3 += w * x.w;
                        }
                    }
                }
                if (fwd) {
                    const float* U = gru_U + j;
                    #pragma unroll 4
                    for (int k = 0; k < 100; ++k) {
                        float u = __ldg(&U[(size_t)k * G3]);
                        float4 h4 = hv[k];
                        ah0 += u * h4.x; ah1 += u * h4.y; ah2 += u * h4.z; ah3 += u * h4.w;
                    }
                } else {
                    const float* U = sW + 19500 + j;
                    #pragma unroll 4
                    for (int k = 0; k < 100; ++k) {
                        float u = U[k * G3];
                        float4 h4 = hv[k];
                        ah0 += u * h4.x; ah1 += u * h4.y; ah2 += u * h4.z; ah3 += u * h4.w;
                    }
                }
                sgx[j*4+0]=ax0; sgx[j*4+1]=ax1; sgx[j*4+2]=ax2; sgx[j*4+3]=ax3;
                sgh[j*4+0]=ah0; sgh[j*4+1]=ah1; sgh[j*4+2]=ah2; sgh[j*4+3]=ah3;
            }
            __syncthreads();
            for (int i = tid; i < 400; i += NTHR) {
                const int j = i >> 2, b = i & 3;
                float z  = sigm(sgx[j*4+b] + sgh[j*4+b]);
                float r  = sigm(sgx[(j+100)*4+b] + sgh[(j+100)*4+b]);
                float nn = tanhf(sgx[(j+200)*4+b] + r * sgh[(j+200)*4+b]);
                float hnew = z * hcur[i] + (1.f - z) * nn;
                hcur[i] = hnew;
                if (!fwd) g_dict[((size_t)dst * BB + b0 + b) * DS + j] = hnew;
            }
            if (!fwd) hb_valid = dst;
            __syncthreads();
        }
    }
}

// out[b][d][t] = state[t][b][d+1]  (reference's literal [:, :, 1:] slice)
__global__ void k_out(float* __restrict__ out) {
    size_t i = (size_t)blockIdx.x * blockDim.x + threadIdx.x;
    if (i >= (size_t)BB * DD * TT) return;
    int t = (int)(i % TT);
    size_t r = i / TT;
    int d = (int)(r % DD);
    int b = (int)(r / DD);
    out[i] = g_state[((size_t)t * BB + b) * ST + d + 1];
}

extern "C" void kernel_launch(void* const* d_in, const int* in_sizes, int n_in,
                              void* d_out, int out_size) {
    const float* a      = (const float*)d_in[0];
    const float* gru_W  = (const float*)d_in[1];
    const float* gru_U  = (const float*)d_in[2];
    const float* gru_b  = (const float*)d_in[3];
    const float* bgru_W = (const float*)d_in[4];
    const float* bgru_U = (const float*)d_in[5];
    const float* bgru_b = (const float*)d_in[6];
    const float* dec_W  = (const float*)d_in[7];
    const float* dec_b  = (const float*)d_in[8];
    const float* mean_W = (const float*)d_in[9];
    const float* mean_b = (const float*)d_in[10];
    float* out = (float*)d_out;

    size_t nbuild = (size_t)TT * BB * ST + (size_t)BB * DS;
    k_build<<<(unsigned)((nbuild + 255) / 256), 256>>>(a);
    k_sched<<<1, 256>>>(a);
    cudaFuncSetAttribute(k_exec, cudaFuncAttributeMaxDynamicSharedMemorySize, SMF * 4);
    k_exec<<<NCTA, NTHR, SMF * 4>>>(gru_W, gru_U, gru_b, bgru_W, bgru_U, bgru_b,
                                    dec_W, dec_b, mean_W, mean_b);
    size_t nout = (size_t)BB * DD * TT;
    k_out<<<(unsigned)((nout + 255) / 256), 256>>>(out);
}

// round 11
// speedup vs baseline: 2.7606x; 2.7606x over previous
#include <cuda_runtime.h>
#include <math.h>

#define TT 256
#define BB 512
#define DD 64
#define G3 300
#define ST 68
#define DS 104
#define NCTA 128
#define NTHR 640
#define MAXOPS 4096
#define SMF 57180   // shared floats in k_exec (228,720 B)

__device__ float g_state[(size_t)TT * BB * ST];
__device__ float g_dict[(size_t)(TT + 1) * BB * DS];
__device__ int4  g_prog[MAXOPS];
__device__ int   g_nops;
__device__ float g_decWt[4 * 50 * 200];   // [lvl][j][k], k contiguous
__device__ float g_meanWt[4 * 64 * 52];   // [lvl][j][k], k padded 50->52

// Repack a[B,D,T,3] -> g_state[t][b][c] (c<64 data, c==64 mask), zero dict[T].
__global__ void k_build(const float* __restrict__ a) {
    size_t i = (size_t)blockIdx.x * blockDim.x + threadIdx.x;
    const size_t n_state = (size_t)TT * BB * ST;
    if (i < n_state) {
        int t = (int)(i % TT);
        size_t r = i / TT;
        int c = (int)(r % ST);
        int b = (int)(r / ST);
        float v = 0.f;
        if (c < DD)       v = a[(((size_t)b * DD + c) * TT + t) * 3];
        else if (c == DD) v = a[(((size_t)b * DD) * TT + t) * 3 + 2];
        g_state[((size_t)t * BB + b) * ST + c] = v;
    } else if (i < n_state + (size_t)BB * DS) {
        g_dict[(size_t)TT * BB * DS + (i - n_state)] = 0.f;
    }
}

// Transpose decoder weights for contiguous-k float4 loads.
__global__ void k_prep(const float* __restrict__ dec_W, const float* __restrict__ mean_W) {
    int i = blockIdx.x * blockDim.x + threadIdx.x;
    if (i < 40000) {                       // decWt[lvl][j][k] = dec_W[lvl][k][j]
        int lvl = i / 10000, r = i % 10000, j = r / 200, k = r % 200;
        g_decWt[i] = dec_W[lvl * 10000 + k * 50 + j];
    } else if (i < 40000 + 13312) {        // meanWt[lvl][j][k] = mean_W[lvl][k][j]
        int m = i - 40000;
        int lvl = m / 3328, r = m % 3328, j = r / 52, k = r % 52;
        g_meanWt[m] = (k < 50) ? mean_W[lvl * 3200 + k * 64 + j] : 0.f;
    }
}

// Replay reference control flow; emit op list.
// op.x: 0=BACK (y=state idx or -1 zeros, z=dict dst, reads dict[z+1])
//       1=FWD  (y=t) | 2=DEC (y=mid, z=hb idx, w=level)
__global__ void k_sched(const float* __restrict__ a) {
    __shared__ unsigned char obs[TT];
    int t = threadIdx.x;
    if (t < TT) obs[t] = (a[(size_t)t * 3 + 2] > 0.5f) ? 1 : 0;
    __syncthreads();
    if (t != 0) return;
    int n = 0;
    for (int k = TT - 1; k >= 2; --k) g_prog[n++] = make_int4(0, k, k, 0);
    g_prog[n++] = make_int4(1, 0, 0, 0);
    int curr = 0;
    while (curr < TT - 1) {
        if (obs[curr + 1]) {
            ++curr;
            g_prog[n++] = make_int4(1, curr, 0, 0);
        } else {
            int next_p = curr + 1;
            while (next_p < TT && !obs[next_p]) ++next_p;
            int step = 1;
            while (curr + 2 * step <= next_p && step <= 8) step *= 2;
            if (step > 1) step /= 2;
            int lvl = 0; { int s = step; while (s > 1) { s >>= 1; ++lvl; } }
            int mid = curr + step;
            g_prog[n++] = make_int4(2, mid, curr + 2 * step, lvl);
            if (step > 1) {
                int right = mid, left = curr + step / 2;
                g_prog[n++] = make_int4(0, right, right, 0);
                for (int i2 = right - 1; i2 >= left; --i2)
                    g_prog[n++] = make_int4(0, -1, i2, 0);
            }
            obs[mid] = 1;
        }
    }
    g_nops = n;
}

__device__ __forceinline__ float sigm(float v) { return 1.f / (1.f + expf(-v)); }

__global__ void __launch_bounds__(NTHR, 1) k_exec(
    const float* __restrict__ gru_W,  const float* __restrict__ gru_U,  const float* __restrict__ gru_b,
    const float* __restrict__ bgru_W, const float* __restrict__ bgru_U, const float* __restrict__ bgru_b,
    const float* __restrict__ dec_b,  const float* __restrict__ mean_b)
{
    extern __shared__ float sm[];
    float* sW  = sm;             // 49500: bgru_W (65x300) + bgru_U (100x300), k-major
    float* sx  = sm + 49500;     // 272:  staged x [k][b]
    float* sh  = sm + 49772;     // 400:  fwd hidden [j*4+b]
    float* shb = sm + 50172;     // 400:  back hidden
    float* sgx = sm + 50572;     // 2400: gate x-part partials [half][j*4+b]
    float* sgh = sm + 52972;     // 2400: gate h-part partials
    float* sdp = sm + 55372;     // 400:  dec hidden partials [half][j*4+b]
    float* sd  = sm + 55772;     // 208:  dec hidden (k padded to 52)
    float* sbf = sm + 55980;     // 600:  fwd bias
    float* sbb = sm + 56580;     // 600:  back bias
    const int tid = threadIdx.x;
    const int b0 = blockIdx.x * 4;

    // hoisted per-thread role constants
    const int cj    = (tid < 600) ? (tid % 300) : 0;   // gate column
    const int chalf = (tid < 600) ? (tid / 300) : 0;   // k-half
    const int dhalf = (tid < 400) ? (tid / 200) : 0;   // dec k-half
    const int dj    = (tid < 400) ? ((tid % 200) >> 2) : 0;
    const int db    = (tid % 200) & 3;
    const int mj    = tid >> 2, mb = tid & 3;          // mean (tid<256)

    for (int i = tid; i < 65 * G3; i += NTHR)  sW[i] = bgru_W[i];
    for (int i = tid; i < 100 * G3; i += NTHR) sW[19500 + i] = bgru_U[i];
    for (int i = tid; i < 600; i += NTHR) { sbf[i] = gru_b[i]; sbb[i] = bgru_b[i]; }
    for (int i = tid; i < 400; i += NTHR) sh[i] = 0.f;
    __syncthreads();

    const int nops = g_nops;
    int hb_valid = -1;
    for (int opi = 0; opi < nops; ++opi) {
        const int4 op = g_prog[opi];
        if (op.x == 2) {
            // ---- DEC ----
            const int mid = op.y, hbi = op.z, lvl = op.w;
            if (hb_valid != hbi) {
                for (int i = tid; i < 400; i += NTHR)
                    shb[i] = g_dict[((size_t)hbi * BB + b0 + (i & 3)) * DS + (i >> 2)];
                hb_valid = hbi;
            }
            __syncthreads();
            if (tid < 400) {   // dec hidden partials: (j, b, half), 100 k each
                float acc = (dhalf == 0) ? __ldg(&dec_b[lvl * 50 + dj]) : 0.f;
                const float4* dwr = (const float4*)(g_decWt + (size_t)lvl * 10000 + dj * 200) + dhalf * 25;
                const float* src = (dhalf == 0) ? sh : shb;
                #pragma unroll 5
                for (int q = 0; q < 25; ++q) {
                    float4 w4 = __ldg(&dwr[q]);
                    int k = q * 4;
                    acc += w4.x * src[k * 4 + db] + w4.y * src[(k + 1) * 4 + db]
                         + w4.z * src[(k + 2) * 4 + db] + w4.w * src[(k + 3) * 4 + db];
                }
                sdp[dhalf * 200 + dj * 4 + db] = acc;
            }
            __syncthreads();
            if (tid < 200) sd[tid] = fmaxf(sdp[tid] + sdp[200 + tid], 0.f);
            else if (tid < 208) sd[tid] = 0.f;
            __syncthreads();
            if (tid < 256) {   // mean: (j, b), 52 padded k
                float acc = __ldg(&mean_b[lvl * DD + mj]);
                const float4* mwr = (const float4*)(g_meanWt + (size_t)lvl * 3328 + mj * 52);
                #pragma unroll 4
                for (int q = 0; q < 13; ++q) {
                    float4 w4 = __ldg(&mwr[q]);
                    int k = q * 4;
                    acc += w4.x * sd[k * 4 + mb] + w4.y * sd[(k + 1) * 4 + mb]
                         + w4.z * sd[(k + 2) * 4 + mb] + w4.w * sd[(k + 3) * 4 + mb];
                }
                float* dst = &g_state[((size_t)mid * BB + b0 + mb) * ST];
                dst[mj] = acc;
                if (mj == 0) dst[DD] = 1.f;
            }
            __syncthreads();
        } else {
            // ---- GRU cell (FWD op.x==1 / BACK op.x==0) ----
            const bool fwd = (op.x == 1);
            const int t = op.y, dst = op.z;
            const bool hasx = (t >= 0);
            const int ID = fwd ? 64 : 65;
            if (hasx) {
                const int off = fwd ? 1 : 0;
                for (int i = tid; i < ID * 4; i += NTHR)
                    sx[(i >> 2) * 4 + (i & 3)] =
                        g_state[((size_t)t * BB + b0 + (i & 3)) * ST + (i >> 2) + off];
            }
            if (!fwd && hb_valid != dst + 1) {
                for (int i = tid; i < 400; i += NTHR)
                    shb[i] = g_dict[((size_t)(dst + 1) * BB + b0 + (i & 3)) * DS + (i >> 2)];
            }
            if (!fwd) hb_valid = dst + 1;
            __syncthreads();
            float* hcur = fwd ? sh : shb;
            if (tid < 600) {
                const float* bias = fwd ? sbf : sbb;
                float ax0, ax1, ax2, ax3, ah0, ah1, ah2, ah3;
                if (chalf == 0) { ax0 = bias[cj]; ah0 = bias[G3 + cj]; }
                else            { ax0 = 0.f;     ah0 = 0.f; }
                ax1 = ax0; ax2 = ax0; ax3 = ax0;
                ah1 = ah0; ah2 = ah0; ah3 = ah0;
                const float4* xv = (const float4*)sx;
                const float4* hv = (const float4*)hcur;
                if (hasx) {
                    const int kmid = (ID + 1) >> 1;
                    const int klo = chalf ? kmid : 0, khi = chalf ? ID : kmid;
                    if (fwd) {
                        const float* W = gru_W + cj;
                        #pragma unroll 8
                        for (int k = klo; k < khi; ++k) {
                            float w = __ldg(&W[(size_t)k * G3]);
                            float4 x = xv[k];
                            ax0 += w * x.x; ax1 += w * x.y; ax2 += w * x.z; ax3 += w * x.w;
                        }
                    } else {
                        const float* W = sW + cj;
                        #pragma unroll 8
                        for (int k = klo; k < khi; ++k) {
                            float w = W[k * G3];
                            float4 x = xv[k];
                            ax0 += w * x.x; ax1 += w * x.y; ax2 += w * x.z; ax3 += w * x.w;
                        }
                    }
                }
                const int ulo = chalf * 50, uhi = ulo + 50;
                if (fwd) {
                    const float* U = gru_U + cj;
                    #pragma unroll 8
                    for (int k = ulo; k < uhi; ++k) {
                        float u = __ldg(&U[(size_t)k * G3]);
                        float4 h4 = hv[k];
                        ah0 += u * h4.x; ah1 += u * h4.y; ah2 += u * h4.z; ah3 += u * h4.w;
                    }
                } else {
                    const float* U = sW + 19500 + cj;
                    #pragma unroll 8
                    for (int k = ulo; k < uhi; ++k) {
                        float u = U[k * G3];
                        float4 h4 = hv[k];
                        ah0 += u * h4.x; ah1 += u * h4.y; ah2 += u * h4.z; ah3 += u * h4.w;
                    }
                }
                ((float4*)(sgx + chalf * 1200))[cj] = make_float4(ax0, ax1, ax2, ax3);
                ((float4*)(sgh + chalf * 1200))[cj] = make_float4(ah0, ah1, ah2, ah3);
            }
            __syncthreads();
            if (tid < 400) {
                const int j = tid >> 2, b = tid & 3;
                float xz = sgx[j * 4 + b]         + sgx[1200 + j * 4 + b];
                float hz = sgh[j * 4 + b]         + sgh[1200 + j * 4 + b];
                float xr = sgx[(j + 100) * 4 + b] + sgx[1200 + (j + 100) * 4 + b];
                float hr = sgh[(j + 100) * 4 + b] + sgh[1200 + (j + 100) * 4 + b];
                float xn = sgx[(j + 200) * 4 + b] + sgx[1200 + (j + 200) * 4 + b];
                float hn = sgh[(j + 200) * 4 + b] + sgh[1200 + (j + 200) * 4 + b];
                float z  = sigm(xz + hz);
                float r  = sigm(xr + hr);
                float nn = tanhf(xn + r * hn);
                float hnew = z * hcur[tid] + (1.f - z) * nn;
                hcur[tid] = hnew;
                if (!fwd) g_dict[((size_t)dst * BB + b0 + b) * DS + j] = hnew;
            }
            if (!fwd) hb_valid = dst;
            __syncthreads();
        }
    }
}

// out[b][d][t] = state[t][b][d+1]
__global__ void k_out(float* __restrict__ out) {
    size_t i = (size_t)blockIdx.x * blockDim.x + threadIdx.x;
    if (i >= (size_t)BB * DD * TT) return;
    int t = (int)(i % TT);
    size_t r = i / TT;
    int d = (int)(r % DD);
    int b = (int)(r / DD);
    out[i] = g_state[((size_t)t * BB + b) * ST + d + 1];
}

extern "C" void kernel_launch(void* const* d_in, const int* in_sizes, int n_in,
                              void* d_out, int out_size) {
    const float* a      = (const float*)d_in[0];
    const float* gru_W  = (const float*)d_in[1];
    const float* gru_U  = (const float*)d_in[2];
    const float* gru_b  = (const float*)d_in[3];
    const float* bgru_W = (const float*)d_in[4];
    const float* bgru_U = (const float*)d_in[5];
    const float* bgru_b = (const float*)d_in[6];
    const float* dec_W  = (const float*)d_in[7];
    const float* dec_b  = (const float*)d_in[8];
    const float* mean_W = (const float*)d_in[9];
    const float* mean_b = (const float*)d_in[10];
    float* out = (float*)d_out;

    size_t nbuild = (size_t)TT * BB * ST + (size_t)BB * DS;
    k_build<<<(unsigned)((nbuild + 255) / 256), 256>>>(a);
    k_prep<<<(40000 + 13312 + 255) / 256, 256>>>(dec_W, mean_W);
    k_sched<<<1, 256>>>(a);
    cudaFuncSetAttribute(k_exec, cudaFuncAttributeMaxDynamicSharedMemorySize, SMF * 4);
    k_exec<<<NCTA, NTHR, SMF * 4>>>(gru_W, gru_U, gru_b, bgru_W, bgru_U, bgru_b,
                                    dec_b, mean_b);
    size_t nout = (size_t)BB * DD * TT;
    k_out<<<(unsigned)((nout + 255) / 256), 256>>>(out);
}

// round 15
// speedup vs baseline: 2.8252x; 1.0234x over previous
#include <cuda_runtime.h>
#include <math.h>

#define TT 256
#define BB 512
#define DD 64
#define G3 300
#define ST 68
#define DS 104
#define NCTA 128
#define NTHR 960
#define MAXOPS 4096
#define SMF 57980   // shared floats in k_exec (231,920 B)

__device__ float g_state[(size_t)TT * BB * ST];
__device__ float g_dict[(size_t)(TT + 1) * BB * DS];
__device__ int4  g_prog[MAXOPS];
__device__ int   g_nops;
__device__ float g_decWt[4 * 50 * 200];   // [lvl][j][k] contiguous k
__device__ float g_meanWt[4 * 64 * 52];   // [lvl][j][k] k padded 50->52

typedef unsigned long long u64;

__device__ __forceinline__ u64 pk2(float a, float b) {
    u64 r; asm("mov.b64 %0,{%1,%2};" : "=l"(r) : "f"(a), "f"(b)); return r;
}
__device__ __forceinline__ u64 ff2(u64 a, u64 b, u64 c) {
    u64 d; asm("fma.rn.f32x2 %0,%1,%2,%3;" : "=l"(d) : "l"(a), "l"(b), "l"(c)); return d;
}
__device__ __forceinline__ u64 ad2(u64 a, u64 b) {
    u64 d; asm("add.rn.f32x2 %0,%1,%2;" : "=l"(d) : "l"(a), "l"(b)); return d;
}
__device__ __forceinline__ float sigm(float v) { return 1.f / (1.f + expf(-v)); }

// Repack a[B,D,T,3] -> g_state[t][b][c] (c<64 data, c==64 mask), zero dict[T].
__global__ void k_build(const float* __restrict__ a) {
    size_t i = (size_t)blockIdx.x * blockDim.x + threadIdx.x;
    const size_t n_state = (size_t)TT * BB * ST;
    if (i < n_state) {
        int t = (int)(i % TT);
        size_t r = i / TT;
        int c = (int)(r % ST);
        int b = (int)(r / ST);
        float v = 0.f;
        if (c < DD)       v = a[(((size_t)b * DD + c) * TT + t) * 3];
        else if (c == DD) v = a[(((size_t)b * DD) * TT + t) * 3 + 2];
        g_state[((size_t)t * BB + b) * ST + c] = v;
    } else if (i < n_state + (size_t)BB * DS) {
        g_dict[(size_t)TT * BB * DS + (i - n_state)] = 0.f;
    }
}

__global__ void k_prep(const float* __restrict__ dec_W, const float* __restrict__ mean_W) {
    int i = blockIdx.x * blockDim.x + threadIdx.x;
    if (i < 40000) {
        int lvl = i / 10000, r = i % 10000, j = r / 200, k = r % 200;
        g_decWt[i] = dec_W[lvl * 10000 + k * 50 + j];
    } else if (i < 40000 + 13312) {
        int m = i - 40000;
        int lvl = m / 3328, r = m % 3328, j = r / 52, k = r % 52;
        g_meanWt[m] = (k < 50) ? mean_W[lvl * 3200 + k * 64 + j] : 0.f;
    }
}

// op.x: 0=BACK (y=state idx or -1 zeros, z=dict dst, reads dict[z+1])
//       1=FWD (y=t) | 2=DEC (y=mid, z=hb idx, w=level)
__global__ void k_sched(const float* __restrict__ a) {
    __shared__ unsigned char obs[TT];
    int t = threadIdx.x;
    if (t < TT) obs[t] = (a[(size_t)t * 3 + 2] > 0.5f) ? 1 : 0;
    __syncthreads();
    if (t != 0) return;
    int n = 0;
    for (int k = TT - 1; k >= 2; --k) g_prog[n++] = make_int4(0, k, k, 0);
    g_prog[n++] = make_int4(1, 0, 0, 0);
    int curr = 0;
    while (curr < TT - 1) {
        if (obs[curr + 1]) {
            ++curr;
            g_prog[n++] = make_int4(1, curr, 0, 0);
        } else {
            int next_p = curr + 1;
            while (next_p < TT && !obs[next_p]) ++next_p;
            int step = 1;
            while (curr + 2 * step <= next_p && step <= 8) step *= 2;
            if (step > 1) step /= 2;
            int lvl = 0; { int s = step; while (s > 1) { s >>= 1; ++lvl; } }
            int mid = curr + step;
            g_prog[n++] = make_int4(2, mid, curr + 2 * step, lvl);
            if (step > 1) {
                int right = mid, left = curr + step / 2;
                g_prog[n++] = make_int4(0, right, right, 0);
                for (int i2 = right - 1; i2 >= left; --i2)
                    g_prog[n++] = make_int4(0, -1, i2, 0);
            }
            obs[mid] = 1;
        }
    }
    g_nops = n;
}

__global__ void __launch_bounds__(NTHR, 1) k_exec(
    const float* __restrict__ gru_W,  const float* __restrict__ gru_U,  const float* __restrict__ gru_b,
    const float* __restrict__ bgru_W, const float* __restrict__ bgru_U, const float* __restrict__ bgru_b,
    const float* __restrict__ dec_b,  const float* __restrict__ mean_b)
{
    extern __shared__ float sm[];
    float* sW  = sm;             // 49500: bgru_W (65x300) + bgru_U (100x300), k-major
    float* sx  = sm + 49500;     // 272:  staged x [k][b]
    float* sh  = sm + 49772;     // 400:  fwd hidden [j*4+b]
    float* shb = sm + 50172;     // 400:  back hidden
    float* sgS = sm + 50572;     // 4800: per-split gate sums (z/r: x+h; n: x-part) [s][c*4+b]
    float* sgN = sm + 55372;     // 1600: per-split n-gate h-part [s][(c-200)*4+b]
    float* sdp = sm + 56972;     // 800:  dec hidden partials [s][j*4+b]
    float* sd  = sm + 57772;     // 208:  dec hidden (k padded to 52)
    const int tid = threadIdx.x;
    const int b0 = blockIdx.x * 4;

    // GRU compute role: 4 splits x 160 threads (warp aligned), 2 cols/thread
    const int gs   = tid / 160;                 // split 0..5 (only <4 used)
    const int slot = tid - gs * 160;
    const bool gact = (tid < 640) && (slot < 150);
    const int c0   = slot * 2;                  // columns c0, c0+1
    // DEC role: 4 splits x 200 threads
    const int dhalf = tid / 200;                // 0..3 (tid<800)
    const int dj    = (tid % 200) >> 2;
    const int db    = tid & 3;
    const int mj    = tid >> 2, mb = tid & 3;   // mean (tid<256)

    for (int i = tid; i < 65 * G3; i += NTHR)  sW[i] = bgru_W[i];
    for (int i = tid; i < 100 * G3; i += NTHR) sW[19500 + i] = bgru_U[i];
    for (int i = tid; i < 400; i += NTHR) sh[i] = 0.f;
    __syncthreads();

    const int nops = g_nops;
    int hb_valid = -1;
    for (int opi = 0; opi < nops; ++opi) {
        const int4 op = g_prog[opi];
        if (op.x == 2) {
            // ---------------- DEC ----------------
            const int mid = op.y, hbi = op.z, lvl = op.w;
            if (hb_valid != hbi) {
                for (int i = tid; i < 400; i += NTHR)
                    shb[i] = g_dict[((size_t)hbi * BB + b0 + (i & 3)) * DS + (i >> 2)];
                hb_valid = hbi;
            }
            __syncthreads();
            if (tid < 800) {   // 4-way k-split over 200, 50 each (k<100: sh, else shb)
                float acc = (dhalf == 0) ? __ldg(&dec_b[lvl * 50 + dj]) : 0.f;
                const float2* dw2 = (const float2*)(g_decWt + (size_t)lvl * 10000 + dj * 200 + dhalf * 50);
                const float* src = (dhalf < 2) ? sh : shb;
                const int lb = (dhalf & 1) * 50;
                #pragma unroll 5
                for (int q = 0; q < 25; ++q) {
                    float2 w2 = __ldg(&dw2[q]);
                    int k = lb + q * 2;
                    acc += w2.x * src[k * 4 + db] + w2.y * src[(k + 1) * 4 + db];
                }
                sdp[dhalf * 200 + dj * 4 + db] = acc;
            }
            __syncthreads();
            if (tid < 200) sd[tid] = fmaxf(sdp[tid] + sdp[200 + tid] + sdp[400 + tid] + sdp[600 + tid], 0.f);
            else if (tid < 208) sd[tid] = 0.f;
            __syncthreads();
            if (tid < 256) {
                float acc = __ldg(&mean_b[lvl * DD + mj]);
                const float4* mwr = (const float4*)(g_meanWt + (size_t)lvl * 3328 + mj * 52);
                #pragma unroll 4
                for (int q = 0; q < 13; ++q) {
                    float4 w4 = __ldg(&mwr[q]);
                    int k = q * 4;
                    acc += w4.x * sd[k * 4 + mb] + w4.y * sd[(k + 1) * 4 + mb]
                         + w4.z * sd[(k + 2) * 4 + mb] + w4.w * sd[(k + 3) * 4 + mb];
                }
                float* dst = &g_state[((size_t)mid * BB + b0 + mb) * ST];
                dst[mj] = acc;
                if (mj == 0) dst[DD] = 1.f;
            }
            __syncthreads();
        } else {
            // ---------------- GRU cell (FWD op.x==1 / BACK op.x==0) ----------------
            const bool fwd = (op.x == 1);
            const int t = op.y, dst = op.z;
            const bool hasx = (t >= 0);
            const int ID = fwd ? 64 : 65;
            if (hasx) {
                const int off = fwd ? 1 : 0;
                for (int i = tid; i < ID * 4; i += NTHR)
                    sx[(i >> 2) * 4 + (i & 3)] =
                        g_state[((size_t)t * BB + b0 + (i & 3)) * ST + (i >> 2) + off];
            }
            if (!fwd && hb_valid != dst + 1) {
                for (int i = tid; i < 400; i += NTHR)
                    shb[i] = g_dict[((size_t)(dst + 1) * BB + b0 + (i & 3)) * DS + (i >> 2)];
            }
            if (!fwd) hb_valid = dst + 1;
            __syncthreads();
            float* hcur = fwd ? sh : shb;
            if (gact) {
                const float* bias = fwd ? gru_b : bgru_b;
                u64 ax0a, ax0b, ax1a, ax1b, ah0a, ah0b, ah1a, ah1b;
                if (gs == 0) {
                    float bx0 = __ldg(&bias[c0]),      bx1 = __ldg(&bias[c0 + 1]);
                    float bh0 = __ldg(&bias[G3 + c0]), bh1 = __ldg(&bias[G3 + c0 + 1]);
                    ax0a = pk2(bx0, bx0); ax0b = ax0a; ax1a = pk2(bx1, bx1); ax1b = ax1a;
                    ah0a = pk2(bh0, bh0); ah0b = ah0a; ah1a = pk2(bh1, bh1); ah1b = ah1a;
                } else {
                    ax0a = ax0b = ax1a = ax1b = 0ull;
                    ah0a = ah0b = ah1a = ah1b = 0ull;
                }
                const ulonglong2* xv = (const ulonglong2*)sx;
                const ulonglong2* hv = (const ulonglong2*)hcur;
                if (hasx) {
                    const int klo = (gs * ID) >> 2, khi = ((gs + 1) * ID) >> 2;
                    const int khiF = (gs == 3) ? ID : khi;
                    if (fwd) {
                        const float2* W = (const float2*)(gru_W + c0);  // stride 150 float2
                        #pragma unroll 8
                        for (int k = klo; k < khiF; ++k) {
                            float2 w = __ldg(&W[(size_t)k * 150]);
                            ulonglong2 x2 = xv[k];
                            u64 w0 = pk2(w.x, w.x), w1 = pk2(w.y, w.y);
                            ax0a = ff2(w0, x2.x, ax0a); ax0b = ff2(w0, x2.y, ax0b);
                            ax1a = ff2(w1, x2.x, ax1a); ax1b = ff2(w1, x2.y, ax1b);
                        }
                    } else {
                        const float2* W = (const float2*)(sW + c0);
                        #pragma unroll 8
                        for (int k = klo; k < khiF; ++k) {
                            float2 w = W[(size_t)k * 150];
                            ulonglong2 x2 = xv[k];
                            u64 w0 = pk2(w.x, w.x), w1 = pk2(w.y, w.y);
                            ax0a = ff2(w0, x2.x, ax0a); ax0b = ff2(w0, x2.y, ax0b);
                            ax1a = ff2(w1, x2.x, ax1a); ax1b = ff2(w1, x2.y, ax1b);
                        }
                    }
                }
                const int ulo = gs * 25, uhi = ulo + 25;
                if (fwd) {
                    const float2* U = (const float2*)(gru_U + c0);
                    #pragma unroll 8
                    for (int k = ulo; k < uhi; ++k) {
                        float2 u = __ldg(&U[(size_t)k * 150]);
                        ulonglong2 h2 = hv[k];
                        u64 u0 = pk2(u.x, u.x), u1 = pk2(u.y, u.y);
                        ah0a = ff2(u0, h2.x, ah0a); ah0b = ff2(u0, h2.y, ah0b);
                        ah1a = ff2(u1, h2.x, ah1a); ah1b = ff2(u1, h2.y, ah1b);
                    }
                } else {
                    const float2* U = (const float2*)(sW + 19500 + c0);
                    #pragma unroll 8
                    for (int k = ulo; k < uhi; ++k) {
                        float2 u = U[(size_t)k * 150];
                        ulonglong2 h2 = hv[k];
                        u64 u0 = pk2(u.x, u.x), u1 = pk2(u.y, u.y);
                        ah0a = ff2(u0, h2.x, ah0a); ah0b = ff2(u0, h2.y, ah0b);
                        ah1a = ff2(u1, h2.x, ah1a); ah1b = ff2(u1, h2.y, ah1b);
                    }
                }
                ulonglong2* outS = (ulonglong2*)(sgS + gs * 1200 + c0 * 4);
                if (c0 < 200) {    // z/r gates: store x+h sums (both cols same side)
                    outS[0] = make_ulonglong2(ad2(ax0a, ah0a), ad2(ax0b, ah0b));
                    outS[1] = make_ulonglong2(ad2(ax1a, ah1a), ad2(ax1b, ah1b));
                } else {           // n gate: keep x and h parts separate
                    outS[0] = make_ulonglong2(ax0a, ax0b);
                    outS[1] = make_ulonglong2(ax1a, ax1b);
                    ulonglong2* outN = (ulonglong2*)(sgN + gs * 400 + (c0 - 200) * 4);
                    outN[0] = make_ulonglong2(ah0a, ah0b);
                    outN[1] = make_ulonglong2(ah1a, ah1b);
                }
            }
            __syncthreads();
            if (tid < 400) {
                const int j = tid >> 2, b = tid & 3;
                float Sz = 0.f, Sr = 0.f, Xn = 0.f, Hn = 0.f;
                #pragma unroll
                for (int s = 0; s < 4; ++s) {
                    Sz += sgS[s * 1200 + j * 4 + b];
                    Sr += sgS[s * 1200 + (j + 100) * 4 + b];
                    Xn += sgS[s * 1200 + (j + 200) * 4 + b];
                    Hn += sgN[s * 400 + j * 4 + b];
                }
                float z  = sigm(Sz);
                float r  = sigm(Sr);
                float nn = tanhf(Xn + r * Hn);
                float hnew = z * hcur[tid] + (1.f - z) * nn;
                hcur[tid] = hnew;
                if (!fwd) g_dict[((size_t)dst * BB + b0 + b) * DS + j] = hnew;
            }
            if (!fwd) hb_valid = dst;
            __syncthreads();
        }
    }
}

// out[b][d][t] = state[t][b][d+1]
__global__ void k_out(float* __restrict__ out) {
    size_t i = (size_t)blockIdx.x * blockDim.x + threadIdx.x;
    if (i >= (size_t)BB * DD * TT) return;
    int t = (int)(i % TT);
    size_t r = i / TT;
    int d = (int)(r % DD);
    int b = (int)(r / DD);
    out[i] = g_state[((size_t)t * BB + b) * ST + d + 1];
}

extern "C" void kernel_launch(void* const* d_in, const int* in_sizes, int n_in,
                              void* d_out, int out_size) {
    const float* a      = (const float*)d_in[0];
    const float* gru_W  = (const float*)d_in[1];
    const float* gru_U  = (const float*)d_in[2];
    const float* gru_b  = (const float*)d_in[3];
    const float* bgru_W = (const float*)d_in[4];
    const float* bgru_U = (const float*)d_in[5];
    const float* bgru_b = (const float*)d_in[6];
    const float* dec_W  = (const float*)d_in[7];
    const float* dec_b  = (const float*)d_in[8];
    const float* mean_W = (const float*)d_in[9];
    const float* mean_b = (const float*)d_in[10];
    float* out = (float*)d_out;

    size_t nbuild = (size_t)TT * BB * ST + (size_t)BB * DS;
    k_build<<<(unsigned)((nbuild + 255) / 256), 256>>>(a);
    k_prep<<<(40000 + 13312 + 255) / 256, 256>>>(dec_W, mean_W);
    k_sched<<<1, 256>>>(a);
    cudaFuncSetAttribute(k_exec, cudaFuncAttributeMaxDynamicSharedMemorySize, SMF * 4);
    k_exec<<<NCTA, NTHR, SMF * 4>>>(gru_W, gru_U, gru_b, bgru_W, bgru_U, bgru_b,
                                    dec_b, mean_b);
    size_t nout = (size_t)BB * DD * TT;
    k_out<<<(unsigned)((nout + 255) / 256), 256>>>(out);
}